// round 6
// baseline (speedup 1.0000x reference)
#include <cuda_runtime.h>
#include <cstdint>

#define RPB 128
#define THREADS 128

static __device__ __forceinline__ uint32_t cvt_tf32(float f) {
    uint32_t r;
    asm("cvt.rn.tf32.f32 %0, %1;" : "=r"(r) : "f"(f));
    return r;
}

static __device__ __forceinline__ void mma_tf32(float* d,
    uint32_t a0, uint32_t a1, uint32_t a2, uint32_t a3,
    uint32_t b0, uint32_t b1)
{
    asm volatile("mma.sync.aligned.m16n8k8.row.col.f32.tf32.tf32.f32 "
        "{%0,%1,%2,%3}, {%4,%5,%6,%7}, {%8,%9}, {%0,%1,%2,%3};"
        : "+f"(d[0]), "+f"(d[1]), "+f"(d[2]), "+f"(d[3])
        : "r"(a0), "r"(a1), "r"(a2), "r"(a3), "r"(b0), "r"(b1));
}

// Stage 1: quad transpose (xor 1). Lane's chunk m = cols 16m + 4*(tigh+2*odd).
static __device__ __forceinline__ void quad_transpose(
    const float (&v)[8][2], float4 (&c)[4], int odd)
{
    #pragma unroll
    for (int m = 0; m < 4; m++) {
        const int j0 = 2 * m, j1 = 2 * m + 1;
        float send0 = odd ? v[j0][0] : v[j1][0];
        float send1 = odd ? v[j0][1] : v[j1][1];
        float own0  = odd ? v[j1][0] : v[j0][0];
        float own1  = odd ? v[j1][1] : v[j0][1];
        float r0 = __shfl_xor_sync(~0u, send0, 1);
        float r1 = __shfl_xor_sync(~0u, send1, 1);
        c[m].x = odd ? r0 : own0;
        c[m].y = odd ? r1 : own1;
        c[m].z = odd ? own0 : r0;
        c[m].w = odd ? own1 : r1;
    }
}

// Stage 2: quad-pair exchange (xor 4) of chunks {1,3}, then 4 STG.128 where
// each 8-lane group writes one full 128B line of one row -> full wavefronts.
static __device__ __forceinline__ void pair_store(
    float4 (&c)[4], float* op, long offE, long offO,
    int colsub, int peven, bool okE, bool okO)
{
    float4 x1, x3;
    x1.x = __shfl_xor_sync(~0u, c[1].x, 4);
    x1.y = __shfl_xor_sync(~0u, c[1].y, 4);
    x1.z = __shfl_xor_sync(~0u, c[1].z, 4);
    x1.w = __shfl_xor_sync(~0u, c[1].w, 4);
    x3.x = __shfl_xor_sync(~0u, c[3].x, 4);
    x3.y = __shfl_xor_sync(~0u, c[3].y, 4);
    x3.z = __shfl_xor_sync(~0u, c[3].z, 4);
    x3.w = __shfl_xor_sync(~0u, c[3].w, 4);
    if (okE) *(float4*)(op + offE + (peven ? 0 : 16) + colsub)      = peven ? c[0] : x1;
    if (okO) *(float4*)(op + offO + (peven ? 16 : 0) + colsub)      = peven ? x1 : c[0];
    if (okE) *(float4*)(op + offE + 32 + (peven ? 0 : 16) + colsub) = peven ? c[2] : x3;
    if (okO) *(float4*)(op + offO + 32 + (peven ? 16 : 0) + colsub) = peven ? x3 : c[2];
}

__global__ __launch_bounds__(THREADS, 4) void assign_mma_kernel(
    const float4* __restrict__ feat4,
    const float4* __restrict__ proto4,
    float* __restrict__ out, int nrows)
{
    __shared__ uint4 A_s[RPB * 16];   // 32 KB
    __shared__ uint4 B_s[64 * 16];    // 16 KB

    const int tid = threadIdx.x;
    const long base = (long)blockIdx.x * RPB;
    const int rows = min(RPB, nrows - (int)base);
    const int cnt4 = rows * 16;

    // ---- stage features (tf32, swizzled); zero-fill OOB rows ----
    const float4* g = feat4 + base * 16;
    #pragma unroll
    for (int i = 0; i < 16; i++) {
        int idx = tid + i * THREADS;
        float4 v = make_float4(0.f, 0.f, 0.f, 0.f);
        if (idx < cnt4) v = g[idx];
        uint4 t;
        t.x = cvt_tf32(v.x); t.y = cvt_tf32(v.y);
        t.z = cvt_tf32(v.z); t.w = cvt_tf32(v.w);
        int r = idx >> 4, c = idx & 15;
        A_s[(r << 4) | (c ^ (r & 7))] = t;
    }
    // ---- stage prototypes ----
    #pragma unroll
    for (int i = 0; i < 8; i++) {
        int idx = tid + i * THREADS;
        float4 v = proto4[idx];
        uint4 t;
        t.x = cvt_tf32(v.x); t.y = cvt_tf32(v.y);
        t.z = cvt_tf32(v.z); t.w = cvt_tf32(v.w);
        int n = idx >> 4, c = idx & 15;
        B_s[(n << 4) | (c ^ (n & 7))] = t;
    }
    __syncthreads();

    const int w = tid >> 5, lane = tid & 31;
    const int gid = lane >> 2, tig = lane & 3;
    const int odd = tig & 1, tigh = tig >> 1;
    const int colsub = 4 * (tigh + 2 * odd);
    const int peven = ((gid & 1) == 0);
    const int sw = gid << 2;
    const int rb = w * 32;

    const uint32_t* As32 = (const uint32_t*)A_s;
    const uint32_t* Bs32 = (const uint32_t*)B_s;

    // ---- GEMM + fused row-norm accumulation ----
    float acc[2][8][4];
    float nrm[2][2] = {{0.f, 0.f}, {0.f, 0.f}};
    #pragma unroll
    for (int ch = 0; ch < 2; ch++)
        #pragma unroll
        for (int j = 0; j < 8; j++)
            #pragma unroll
            for (int e = 0; e < 4; e++) acc[ch][j][e] = 0.f;

    #pragma unroll
    for (int ks = 0; ks < 8; ks++) {
        int o0 = (ks * 8 + tig) ^ sw;
        int o1 = (ks * 8 + tig + 4) ^ sw;
        uint32_t b0[8], b1[8];
        #pragma unroll
        for (int j = 0; j < 8; j++) {
            int n = j * 8 + gid;
            b0[j] = Bs32[n * 64 + o0];
            b1[j] = Bs32[n * 64 + o1];
        }
        #pragma unroll
        for (int ch = 0; ch < 2; ch++) {
            int r = rb + ch * 16 + gid;
            uint32_t a0 = As32[r * 64 + o0];
            uint32_t a1 = As32[(r + 8) * 64 + o0];
            uint32_t a2 = As32[r * 64 + o1];
            uint32_t a3 = As32[(r + 8) * 64 + o1];
            float f0 = __uint_as_float(a0), f1 = __uint_as_float(a1);
            float f2 = __uint_as_float(a2), f3 = __uint_as_float(a3);
            nrm[ch][0] += f0 * f0 + f2 * f2;   // row r
            nrm[ch][1] += f1 * f1 + f3 * f3;   // row r+8
            #pragma unroll
            for (int j = 0; j < 8; j++)
                mma_tf32(acc[ch][j], a0, a1, a2, a3, b0[j], b1[j]);
        }
    }

    // ---- scales: quad-reduce over tig; sc = 5 / max(||f||, eps)  (tau=0.2) ----
    float sc[2][2];
    #pragma unroll
    for (int ch = 0; ch < 2; ch++)
        #pragma unroll
        for (int hf = 0; hf < 2; hf++) {
            float s = nrm[ch][hf];
            s += __shfl_xor_sync(~0u, s, 1);
            s += __shfl_xor_sync(~0u, s, 2);
            sc[ch][hf] = 5.0f / fmaxf(sqrtf(s), 1e-8f);
        }

    // ---- epilogue ----
    #pragma unroll
    for (int ch = 0; ch < 2; ch++) {
        #pragma unroll
        for (int hf = 0; hf < 2; hf++) {
            int rE = rb + ch * 16 + hf * 8 + (gid & ~1);
            int rO = rE + 1;
            float scv = sc[ch][hf];
            bool okE = (rE < rows), okO = (rO < rows);
            long offE = (base + rE) * 64;
            long offO = (base + rO) * 64;

            float lg[8][2], ex[8][2];
            float s = 0.f;
            #pragma unroll
            for (int j = 0; j < 8; j++) {
                lg[j][0] = acc[ch][j][2 * hf]     * scv;
                lg[j][1] = acc[ch][j][2 * hf + 1] * scv;
                ex[j][0] = __expf(lg[j][0]);       // |logit| <= 5
                ex[j][1] = __expf(lg[j][1]);
                s += ex[j][0] + ex[j][1];
            }
            s += __shfl_xor_sync(~0u, s, 1);
            s += __shfl_xor_sync(~0u, s, 2);
            float inv = 1.0f / s;
            #pragma unroll
            for (int j = 0; j < 8; j++) {
                ex[j][0] *= inv;
                ex[j][1] *= inv;
            }

            float4 c[4];
            quad_transpose(lg, c, odd);
            pair_store(c, out, offE, offO, colsub, peven, okE, okO);
            quad_transpose(ex, c, odd);
            pair_store(c, out + (long)nrows * 64, offE, offO, colsub, peven, okE, okO);
        }
    }
}

extern "C" void kernel_launch(void* const* d_in, const int* in_sizes, int n_in,
                              void* d_out, int out_size) {
    const float4* feat4  = (const float4*)d_in[0];
    const float4* proto4 = (const float4*)d_in[1];
    float* out = (float*)d_out;
    int nrows = in_sizes[0] / 64;
    int grid = (nrows + RPB - 1) / RPB;
    assign_mma_kernel<<<grid, THREADS>>>(feat4, proto4, out, nrows);
}

// round 7
// speedup vs baseline: 1.0729x; 1.0729x over previous
#include <cuda_runtime.h>
#include <cstdint>

#define RPB 128
#define THREADS 256

static __device__ __forceinline__ uint32_t cvt_tf32(float f) {
    uint32_t r;
    asm("cvt.rn.tf32.f32 %0, %1;" : "=r"(r) : "f"(f));
    return r;
}

static __device__ __forceinline__ void mma_tf32(float* d,
    uint32_t a0, uint32_t a1, uint32_t a2, uint32_t a3,
    uint32_t b0, uint32_t b1)
{
    asm volatile("mma.sync.aligned.m16n8k8.row.col.f32.tf32.tf32.f32 "
        "{%0,%1,%2,%3}, {%4,%5,%6,%7}, {%8,%9}, {%0,%1,%2,%3};"
        : "+f"(d[0]), "+f"(d[1]), "+f"(d[2]), "+f"(d[3])
        : "r"(a0), "r"(a1), "r"(a2), "r"(a3), "r"(b0), "r"(b1));
}

// Stage 1: quad transpose (xor 1). Lane's chunk m = cols 16m + 4*(tigh+2*odd).
static __device__ __forceinline__ void quad_transpose(
    const float (&v)[8][2], float4 (&c)[4], int odd)
{
    #pragma unroll
    for (int m = 0; m < 4; m++) {
        const int j0 = 2 * m, j1 = 2 * m + 1;
        float send0 = odd ? v[j0][0] : v[j1][0];
        float send1 = odd ? v[j0][1] : v[j1][1];
        float own0  = odd ? v[j1][0] : v[j0][0];
        float own1  = odd ? v[j1][1] : v[j0][1];
        float r0 = __shfl_xor_sync(~0u, send0, 1);
        float r1 = __shfl_xor_sync(~0u, send1, 1);
        c[m].x = odd ? r0 : own0;
        c[m].y = odd ? r1 : own1;
        c[m].z = odd ? own0 : r0;
        c[m].w = odd ? own1 : r1;
    }
}

// Stage 2: quad-pair exchange (xor 4) of chunks {1,3}; each 8-lane group then
// writes one full 128B line of one row per STG.128 -> full store wavefronts.
static __device__ __forceinline__ void pair_store(
    float4 (&c)[4], float* op, long offE, long offO,
    int colsub, int peven, bool okE, bool okO)
{
    float4 x1, x3;
    x1.x = __shfl_xor_sync(~0u, c[1].x, 4);
    x1.y = __shfl_xor_sync(~0u, c[1].y, 4);
    x1.z = __shfl_xor_sync(~0u, c[1].z, 4);
    x1.w = __shfl_xor_sync(~0u, c[1].w, 4);
    x3.x = __shfl_xor_sync(~0u, c[3].x, 4);
    x3.y = __shfl_xor_sync(~0u, c[3].y, 4);
    x3.z = __shfl_xor_sync(~0u, c[3].z, 4);
    x3.w = __shfl_xor_sync(~0u, c[3].w, 4);
    if (okE) *(float4*)(op + offE + (peven ? 0 : 16) + colsub)      = peven ? c[0] : x1;
    if (okO) *(float4*)(op + offO + (peven ? 16 : 0) + colsub)      = peven ? x1 : c[0];
    if (okE) *(float4*)(op + offE + 32 + (peven ? 0 : 16) + colsub) = peven ? c[2] : x3;
    if (okO) *(float4*)(op + offO + 32 + (peven ? 16 : 0) + colsub) = peven ? x3 : c[2];
}

// 256 threads, 8 warps; warp w owns 16 rows (w*16..+15) x all 64 protos.
__global__ __launch_bounds__(THREADS, 3) void assign_mma_kernel(
    const float4* __restrict__ feat4,
    const float4* __restrict__ proto4,
    float* __restrict__ out, int nrows)
{
    __shared__ uint4 A_s[RPB * 16];   // 32 KB
    __shared__ uint4 B_s[64 * 16];    // 16 KB

    const int tid = threadIdx.x;
    const long base = (long)blockIdx.x * RPB;
    const int rows = min(RPB, nrows - (int)base);
    const int cnt4 = rows * 16;

    // ---- stage features (tf32, swizzled); zero-fill OOB rows ----
    const float4* g = feat4 + base * 16;
    #pragma unroll
    for (int i = 0; i < 8; i++) {
        int idx = tid + i * THREADS;
        float4 v = make_float4(0.f, 0.f, 0.f, 0.f);
        if (idx < cnt4) v = g[idx];
        uint4 t;
        t.x = cvt_tf32(v.x); t.y = cvt_tf32(v.y);
        t.z = cvt_tf32(v.z); t.w = cvt_tf32(v.w);
        int r = idx >> 4, c = idx & 15;
        A_s[(r << 4) | (c ^ (r & 7))] = t;
    }
    // ---- stage prototypes ----
    #pragma unroll
    for (int i = 0; i < 4; i++) {
        int idx = tid + i * THREADS;
        float4 v = proto4[idx];
        uint4 t;
        t.x = cvt_tf32(v.x); t.y = cvt_tf32(v.y);
        t.z = cvt_tf32(v.z); t.w = cvt_tf32(v.w);
        int n = idx >> 4, c = idx & 15;
        B_s[(n << 4) | (c ^ (n & 7))] = t;
    }
    __syncthreads();

    const int w = tid >> 5, lane = tid & 31;
    const int gid = lane >> 2, tig = lane & 3;
    const int odd = tig & 1, tigh = tig >> 1;
    const int colsub = 4 * (tigh + 2 * odd);
    const int peven = ((gid & 1) == 0);
    const int sw = gid << 2;
    const int rb = w * 16;

    const uint32_t* As32 = (const uint32_t*)A_s;
    const uint32_t* Bs32 = (const uint32_t*)B_s;

    // ---- GEMM + fused row-norm accumulation ----
    float acc[8][4];
    float nrm[2] = {0.f, 0.f};
    #pragma unroll
    for (int j = 0; j < 8; j++)
        #pragma unroll
        for (int e = 0; e < 4; e++) acc[j][e] = 0.f;

    #pragma unroll
    for (int ks = 0; ks < 8; ks++) {
        int o0 = (ks * 8 + tig) ^ sw;
        int o1 = (ks * 8 + tig + 4) ^ sw;
        int r = rb + gid;
        uint32_t a0 = As32[r * 64 + o0];
        uint32_t a1 = As32[(r + 8) * 64 + o0];
        uint32_t a2 = As32[r * 64 + o1];
        uint32_t a3 = As32[(r + 8) * 64 + o1];
        float f0 = __uint_as_float(a0), f1 = __uint_as_float(a1);
        float f2 = __uint_as_float(a2), f3 = __uint_as_float(a3);
        nrm[0] += f0 * f0 + f2 * f2;   // row r
        nrm[1] += f1 * f1 + f3 * f3;   // row r+8
        #pragma unroll
        for (int j = 0; j < 8; j++) {
            int n = j * 8 + gid;
            uint32_t b0 = Bs32[n * 64 + o0];
            uint32_t b1 = Bs32[n * 64 + o1];
            mma_tf32(acc[j], a0, a1, a2, a3, b0, b1);
        }
    }

    // ---- scales: quad-reduce; sc = 5 / max(||f||, eps)  (tau=0.2) ----
    float sc[2];
    #pragma unroll
    for (int hf = 0; hf < 2; hf++) {
        float s = nrm[hf];
        s += __shfl_xor_sync(~0u, s, 1);
        s += __shfl_xor_sync(~0u, s, 2);
        sc[hf] = 5.0f / fmaxf(sqrtf(s), 1e-8f);
    }

    // ---- epilogue: scale, exp, quad-reduce sum, full-line stores ----
    #pragma unroll
    for (int hf = 0; hf < 2; hf++) {
        int rE = rb + hf * 8 + (gid & ~1);
        int rO = rE + 1;
        float scv = sc[hf];
        bool okE = (rE < rows), okO = (rO < rows);
        long offE = (base + rE) * 64;
        long offO = (base + rO) * 64;

        float lg[8][2], ex[8][2];
        float s = 0.f;
        #pragma unroll
        for (int j = 0; j < 8; j++) {
            lg[j][0] = acc[j][2 * hf]     * scv;
            lg[j][1] = acc[j][2 * hf + 1] * scv;
            ex[j][0] = __expf(lg[j][0]);       // |logit| <= 5
            ex[j][1] = __expf(lg[j][1]);
            s += ex[j][0] + ex[j][1];
        }
        s += __shfl_xor_sync(~0u, s, 1);
        s += __shfl_xor_sync(~0u, s, 2);
        float inv = 1.0f / s;
        #pragma unroll
        for (int j = 0; j < 8; j++) {
            ex[j][0] *= inv;
            ex[j][1] *= inv;
        }

        float4 c[4];
        quad_transpose(lg, c, odd);
        pair_store(c, out, offE, offO, colsub, peven, okE, okO);
        quad_transpose(ex, c, odd);
        pair_store(c, out + (long)nrows * 64, offE, offO, colsub, peven, okE, okO);
    }
}

extern "C" void kernel_launch(void* const* d_in, const int* in_sizes, int n_in,
                              void* d_out, int out_size) {
    const float4* feat4  = (const float4*)d_in[0];
    const float4* proto4 = (const float4*)d_in[1];
    float* out = (float*)d_out;
    int nrows = in_sizes[0] / 64;
    int grid = (nrows + RPB - 1) / RPB;
    assign_mma_kernel<<<grid, THREADS>>>(feat4, proto4, out, nrows);
}